// round 1
// baseline (speedup 1.0000x reference)
#include <cuda_runtime.h>
#include <math.h>

// Problem constants
#define BATCH   64
#define HDIM    28
#define WDIM    28
#define C_      512
#define HEADS_  16
#define WS_     7
#define SHIFT_  3
#define MLPD    2048
#define HD_     32
#define W2_     49
#define NW_     16
#define HW_     784
#define MTOK    50176   // BATCH*HW
#define NWIN    1024    // BATCH*NW

// Scratch (device globals: no allocation allowed in kernel_launch)
__device__ float g_win[MTOK * C_];
__device__ float g_q[MTOK * C_];
__device__ float g_k[MTOK * C_];
__device__ float g_v[MTOK * C_];
__device__ float g_ctx[MTOK * C_];
__device__ float g_x1[MTOK * C_];
__device__ float g_h2[MTOK * C_];
__device__ float g_mid[(size_t)MTOK * MLPD];

// Map a window-partition row index m = (b, window, token) to the source/dest
// token row in the (unshifted) [B, H*W] layout. Forward shift is roll(-3,-3):
// shifted[r] = orig[(r+3) % 28]. The same map serves gather (LN1) and scatter
// (attention output reverse + un-shift).
__device__ __forceinline__ int map_row(int m) {
    int bb  = m / HW_;
    int rem = m - bb * HW_;
    int w   = rem / W2_;
    int t   = rem - w * W2_;
    int wh = w >> 2, ww = w & 3;
    int th = t / WS_, tw = t - th * WS_;
    int r = wh * WS_ + th + SHIFT_; if (r >= HDIM) r -= HDIM;
    int c = ww * WS_ + tw + SHIFT_; if (c >= WDIM) c -= WDIM;
    return bb * HW_ + r * WDIM + c;
}

// LayerNorm over C=512, one block per token row, 128 threads * float4.
// gather=1: out row m is LN of input row map_row(m)  (LN is per-token, so
// LN-then-shift == shift-then-LN).
__global__ __launch_bounds__(128) void ln_kernel(
    const float* __restrict__ in, const float* __restrict__ g,
    const float* __restrict__ b, float* __restrict__ out, int gather)
{
    int m = blockIdx.x;
    int src = gather ? map_row(m) : m;
    int tid = threadIdx.x;

    float4 xv = ((const float4*)(in + (size_t)src * C_))[tid];
    float s  = xv.x + xv.y + xv.z + xv.w;
    float s2 = xv.x*xv.x + xv.y*xv.y + xv.z*xv.z + xv.w*xv.w;
    #pragma unroll
    for (int off = 16; off; off >>= 1) {
        s  += __shfl_xor_sync(0xffffffffu, s,  off);
        s2 += __shfl_xor_sync(0xffffffffu, s2, off);
    }
    __shared__ float red[8];
    int wid = tid >> 5;
    if ((tid & 31) == 0) { red[wid] = s; red[4 + wid] = s2; }
    __syncthreads();
    s  = red[0] + red[1] + red[2] + red[3];
    s2 = red[4] + red[5] + red[6] + red[7];
    float mu   = s * (1.0f / C_);
    float var  = fmaf(-mu, mu, s2 * (1.0f / C_));
    float rstd = rsqrtf(var + 1e-5f);

    float4 gv = ((const float4*)g)[tid];
    float4 bv = ((const float4*)b)[tid];
    float4 o;
    o.x = (xv.x - mu) * rstd * gv.x + bv.x;
    o.y = (xv.y - mu) * rstd * gv.y + bv.y;
    o.z = (xv.z - mu) * rstd * gv.z + bv.z;
    o.w = (xv.w - mu) * rstd * gv.w + bv.w;
    ((float4*)(out + (size_t)m * C_))[tid] = o;
}

// Classic fp32 SGEMM: C[M,N] = A[M,K] @ B[K,N] + bias, with epilogue modes.
// BM=BN=128, BK=8, 256 threads, 8x8 microtile. M,N,K are exact multiples of
// the tile sizes here (M=50176=392*128; N,K in {512,2048}).
// mode 0: plain            mode 1: exact GELU
// mode 2: += res[m]        mode 3: scatter row via map_row(m), += res[out_row]
#define BM 128
#define BN 128
#define BK 8
#define TM 8
#define TN 8

__global__ __launch_bounds__(256) void sgemm_kernel(
    const float* __restrict__ A, const float* __restrict__ Bm,
    const float* __restrict__ bias, float* __restrict__ C,
    int M, int N, int K, int mode, const float* __restrict__ res)
{
    __shared__ float As[BK][BM];
    __shared__ float Bs[BK][BN];

    int cRow = blockIdx.y, cCol = blockIdx.x;
    int tid = threadIdx.x;
    int tRow = (tid >> 4) * TM;   // 0..120
    int tCol = (tid & 15) * TN;   // 0..120

    const float* Ab = A  + (size_t)cRow * BM * K;
    const float* Bb = Bm + (size_t)cCol * BN;

    int aRow = tid >> 1,  aCol = (tid & 1)  * 4;   // 128x8 A tile, float4
    int bRow = tid >> 5,  bCol = (tid & 31) * 4;   // 8x128  B tile, float4

    float acc[TM][TN] = {};
    float regA[TM], regB[TN];

    for (int k0 = 0; k0 < K; k0 += BK) {
        float4 av = *(const float4*)(Ab + (size_t)aRow * K + k0 + aCol);
        As[aCol + 0][aRow] = av.x;
        As[aCol + 1][aRow] = av.y;
        As[aCol + 2][aRow] = av.z;
        As[aCol + 3][aRow] = av.w;
        float4 bv = *(const float4*)(Bb + (size_t)(k0 + bRow) * N + bCol);
        *(float4*)&Bs[bRow][bCol] = bv;
        __syncthreads();

        #pragma unroll
        for (int kk = 0; kk < BK; kk++) {
            #pragma unroll
            for (int i = 0; i < TM; i++) regA[i] = As[kk][tRow + i];
            #pragma unroll
            for (int j = 0; j < TN; j++) regB[j] = Bs[kk][tCol + j];
            #pragma unroll
            for (int i = 0; i < TM; i++)
                #pragma unroll
                for (int j = 0; j < TN; j++)
                    acc[i][j] = fmaf(regA[i], regB[j], acc[i][j]);
        }
        __syncthreads();
    }

    #pragma unroll
    for (int i = 0; i < TM; i++) {
        int m = cRow * BM + tRow + i;
        int outm = (mode == 3) ? map_row(m) : m;
        #pragma unroll
        for (int j = 0; j < TN; j++) {
            int n = cCol * BN + tCol + j;
            float val = acc[i][j] + bias[n];
            if (mode == 1) {
                val = 0.5f * val * (1.0f + erff(val * 0.70710678118654752f));
            } else if (mode == 2) {
                val += res[(size_t)m * N + n];
            } else if (mode == 3) {
                val += res[(size_t)outm * N + n];
            }
            C[(size_t)outm * N + n] = val;
        }
    }
}

// Windowed attention: one block per (window, head). q/k/v tiles (49x32) and
// the 49x49 score matrix live in smem. Adds relative-position bias and the
// shifted-window mask (computed inline from region bands), softmax, then PV.
__global__ __launch_bounds__(128) void attn_kernel(
    const float* __restrict__ q, const float* __restrict__ k,
    const float* __restrict__ v, const float* __restrict__ rel_table,
    const int* __restrict__ rel_index, float* __restrict__ ctx)
{
    __shared__ float qs[W2_][HD_];
    __shared__ float ks[W2_][HD_];
    __shared__ float vs[W2_][HD_];
    __shared__ float sc[W2_][W2_ + 1];
    __shared__ int   grp[W2_];

    int blk  = blockIdx.x;
    int head = blk & (HEADS_ - 1);
    int win  = blk >> 4;
    int w    = win & (NW_ - 1);
    int tid  = threadIdx.x;

    const size_t base = (size_t)win * W2_ * C_ + head * HD_;
    for (int idx = tid; idx < W2_ * HD_; idx += 128) {
        int t = idx >> 5, d = idx & 31;
        size_t off = base + (size_t)t * C_ + d;
        qs[t][d] = q[off];
        ks[t][d] = k[off];
        vs[t][d] = v[off];
    }
    if (tid < W2_) {
        int wh = w >> 2, ww = w & 3;
        int r = wh * WS_ + tid / WS_;
        int c = ww * WS_ + tid % WS_;
        int br = (r < HDIM - WS_) ? 0 : ((r < HDIM - SHIFT_) ? 1 : 2);
        int bc = (c < WDIM - WS_) ? 0 : ((c < WDIM - SHIFT_) ? 1 : 2);
        grp[tid] = br * 3 + bc;
    }
    __syncthreads();

    const float scale = 0.17677669529663687f; // 1/sqrt(32)
    for (int idx = tid; idx < W2_ * W2_; idx += 128) {
        int i = idx / W2_, j = idx - i * W2_;
        float acc = 0.0f;
        #pragma unroll
        for (int d = 0; d < HD_; d++) acc = fmaf(qs[i][d], ks[j][d], acc);
        float bias = rel_table[rel_index[idx] * HEADS_ + head];
        float mask = (grp[i] != grp[j]) ? -100.0f : 0.0f;
        sc[i][j] = acc * scale + bias + mask;
    }
    __syncthreads();

    if (tid < W2_) {
        float mx = -1e30f;
        #pragma unroll 7
        for (int j = 0; j < W2_; j++) mx = fmaxf(mx, sc[tid][j]);
        float sum = 0.0f;
        #pragma unroll 7
        for (int j = 0; j < W2_; j++) {
            float e = __expf(sc[tid][j] - mx);
            sc[tid][j] = e;
            sum += e;
        }
        float inv = 1.0f / sum;
        #pragma unroll 7
        for (int j = 0; j < W2_; j++) sc[tid][j] *= inv;
    }
    __syncthreads();

    for (int idx = tid; idx < W2_ * HD_; idx += 128) {
        int i = idx >> 5, d = idx & 31;
        float acc = 0.0f;
        #pragma unroll 7
        for (int j = 0; j < W2_; j++) acc = fmaf(sc[i][j], vs[j][d], acc);
        ctx[base + (size_t)i * C_ + d] = acc;
    }
}

extern "C" void kernel_launch(void* const* d_in, const int* in_sizes, int n_in,
                              void* d_out, int out_size)
{
    const float* x         = (const float*)d_in[0];
    const float* g1        = (const float*)d_in[1];
    const float* b1        = (const float*)d_in[2];
    const float* wq        = (const float*)d_in[3];
    const float* bq        = (const float*)d_in[4];
    const float* wk        = (const float*)d_in[5];
    const float* bk        = (const float*)d_in[6];
    const float* wv        = (const float*)d_in[7];
    const float* bv        = (const float*)d_in[8];
    const float* rel_table = (const float*)d_in[9];
    const float* wo        = (const float*)d_in[10];
    const float* bo        = (const float*)d_in[11];
    const float* g2        = (const float*)d_in[12];
    const float* b2        = (const float*)d_in[13];
    const float* wi        = (const float*)d_in[14];
    const float* bi        = (const float*)d_in[15];
    const float* w_out     = (const float*)d_in[16];
    const float* b_out     = (const float*)d_in[17];
    const int*   rel_index = (const int*)d_in[18];
    float* out = (float*)d_out;

    float *p_win, *p_q, *p_k, *p_v, *p_ctx, *p_x1, *p_h2, *p_mid;
    cudaGetSymbolAddress((void**)&p_win, g_win);
    cudaGetSymbolAddress((void**)&p_q,   g_q);
    cudaGetSymbolAddress((void**)&p_k,   g_k);
    cudaGetSymbolAddress((void**)&p_v,   g_v);
    cudaGetSymbolAddress((void**)&p_ctx, g_ctx);
    cudaGetSymbolAddress((void**)&p_x1,  g_x1);
    cudaGetSymbolAddress((void**)&p_h2,  g_h2);
    cudaGetSymbolAddress((void**)&p_mid, g_mid);

    // 1. LN1 + cyclic shift + window partition (gather)
    ln_kernel<<<MTOK, 128>>>(x, g1, b1, p_win, 1);

    // 2-4. QKV projections
    dim3 gC(C_ / BN, MTOK / BM);
    sgemm_kernel<<<gC, 256>>>(p_win, wq, bq, p_q, MTOK, C_, C_, 0, nullptr);
    sgemm_kernel<<<gC, 256>>>(p_win, wk, bk, p_k, MTOK, C_, C_, 0, nullptr);
    sgemm_kernel<<<gC, 256>>>(p_win, wv, bv, p_v, MTOK, C_, C_, 0, nullptr);

    // 5. windowed attention (scores + bias + mask + softmax + PV)
    attn_kernel<<<NWIN * HEADS_, 128>>>(p_q, p_k, p_v, rel_table, rel_index, p_ctx);

    // 6. output projection + window reverse + un-shift scatter + residual(x)
    sgemm_kernel<<<gC, 256>>>(p_ctx, wo, bo, p_x1, MTOK, C_, C_, 3, x);

    // 7. LN2
    ln_kernel<<<MTOK, 128>>>(p_x1, g2, b2, p_h2, 0);

    // 8. MLP up-projection + exact GELU
    dim3 gM(MLPD / BN, MTOK / BM);
    sgemm_kernel<<<gM, 256>>>(p_h2, wi, bi, p_mid, MTOK, MLPD, C_, 1, nullptr);

    // 9. MLP down-projection + residual(x1) -> final output
    sgemm_kernel<<<gC, 256>>>(p_mid, w_out, b_out, out, MTOK, C_, MLPD, 2, p_x1);
}

// round 2
// speedup vs baseline: 2.0880x; 2.0880x over previous
#include <cuda_runtime.h>
#include <math.h>
#include <stdint.h>

// Problem constants
#define BATCH   64
#define HDIM    28
#define WDIM    28
#define C_      512
#define HEADS_  16
#define WS_     7
#define SHIFT_  3
#define MLPD    2048
#define HD_     32
#define W2_     49
#define NW_     16
#define HW_     784
#define MTOK    50176   // BATCH*HW
#define NWIN    1024    // BATCH*NW

// Scratch (device globals: no allocation allowed in kernel_launch)
__device__ float g_win[MTOK * C_];
__device__ float g_q[MTOK * C_];
__device__ float g_k[MTOK * C_];
__device__ float g_v[MTOK * C_];
__device__ float g_ctx[MTOK * C_];
__device__ float g_x1[MTOK * C_];
__device__ float g_h2[MTOK * C_];
__device__ float g_mid[(size_t)MTOK * MLPD];

// Map window-partition row m -> token row in the unshifted [B,H*W] layout.
__device__ __forceinline__ int map_row(int m) {
    int bb  = m / HW_;
    int rem = m - bb * HW_;
    int w   = rem / W2_;
    int t   = rem - w * W2_;
    int wh = w >> 2, ww = w & 3;
    int th = t / WS_, tw = t - th * WS_;
    int r = wh * WS_ + th + SHIFT_; if (r >= HDIM) r -= HDIM;
    int c = ww * WS_ + tw + SHIFT_; if (c >= WDIM) c -= WDIM;
    return bb * HW_ + r * WDIM + c;
}

// LayerNorm over C=512, one block per token row.
__global__ __launch_bounds__(128) void ln_kernel(
    const float* __restrict__ in, const float* __restrict__ g,
    const float* __restrict__ b, float* __restrict__ out, int gather)
{
    int m = blockIdx.x;
    int src = gather ? map_row(m) : m;
    int tid = threadIdx.x;

    float4 xv = ((const float4*)(in + (size_t)src * C_))[tid];
    float s  = xv.x + xv.y + xv.z + xv.w;
    float s2 = xv.x*xv.x + xv.y*xv.y + xv.z*xv.z + xv.w*xv.w;
    #pragma unroll
    for (int off = 16; off; off >>= 1) {
        s  += __shfl_xor_sync(0xffffffffu, s,  off);
        s2 += __shfl_xor_sync(0xffffffffu, s2, off);
    }
    __shared__ float red[8];
    int wid = tid >> 5;
    if ((tid & 31) == 0) { red[wid] = s; red[4 + wid] = s2; }
    __syncthreads();
    s  = red[0] + red[1] + red[2] + red[3];
    s2 = red[4] + red[5] + red[6] + red[7];
    float mu   = s * (1.0f / C_);
    float var  = fmaf(-mu, mu, s2 * (1.0f / C_));
    float rstd = rsqrtf(var + 1e-5f);

    float4 gv = ((const float4*)g)[tid];
    float4 bv = ((const float4*)b)[tid];
    float4 o;
    o.x = (xv.x - mu) * rstd * gv.x + bv.x;
    o.y = (xv.y - mu) * rstd * gv.y + bv.y;
    o.z = (xv.z - mu) * rstd * gv.z + bv.z;
    o.w = (xv.w - mu) * rstd * gv.w + bv.w;
    ((float4*)(out + (size_t)m * C_))[tid] = o;
}

// ---------------------------------------------------------------------------
// TF32 tensor-core GEMM: C[M,N] = A[M,K] @ B[K,N] + bias, epilogue modes.
// 256 threads = 8 warps (2 x 4), block tile 128x128, BK=16, warp tile 64x32.
// mma.sync.aligned.m16n8k8.row.col.f32.tf32.tf32.f32, fp32 accumulate.
// mode 0: plain   mode 1: exact GELU   mode 2: += res[m]
// mode 3: scatter row via map_row(m), += res[out_row]
// ---------------------------------------------------------------------------
#define BM 128
#define BN 128
#define BKT 16
#define APAD 4
#define BPAD 8

__device__ __forceinline__ uint32_t f2tf(float f) {
    uint32_t u;
    asm("cvt.rna.tf32.f32 %0, %1;" : "=r"(u) : "f"(f));
    return u;
}

__device__ __forceinline__ void mma_tf32(float c[4], uint32_t a0, uint32_t a1,
                                         uint32_t a2, uint32_t a3,
                                         uint32_t b0, uint32_t b1) {
    asm volatile(
        "mma.sync.aligned.m16n8k8.row.col.f32.tf32.tf32.f32 "
        "{%0,%1,%2,%3}, {%4,%5,%6,%7}, {%8,%9}, {%0,%1,%2,%3};"
        : "+f"(c[0]), "+f"(c[1]), "+f"(c[2]), "+f"(c[3])
        : "r"(a0), "r"(a1), "r"(a2), "r"(a3), "r"(b0), "r"(b1));
}

__global__ __launch_bounds__(256) void tgemm_kernel(
    const float* __restrict__ A, const float* __restrict__ Bm,
    const float* __restrict__ bias, float* __restrict__ C,
    int M, int N, int K, int mode, const float* __restrict__ res)
{
    __shared__ float As[BM][BKT + APAD];   // [m][k]
    __shared__ float Bs[BKT][BN + BPAD];   // [k][n]

    const int cRow = blockIdx.y, cCol = blockIdx.x;
    const int tid  = threadIdx.x;
    const int wid  = tid >> 5;
    const int lane = tid & 31;
    const int wm   = wid >> 2;       // 0..1  (warp row -> 64 rows)
    const int wn   = wid & 3;        // 0..3  (warp col -> 32 cols)
    const int grp  = lane >> 2;      // 0..7
    const int tig  = lane & 3;       // 0..3

    const float* Ab = A  + (size_t)cRow * BM * K;
    const float* Bb = Bm + (size_t)cCol * BN;

    // gmem load mapping
    const int am = tid >> 1;               // 0..127
    const int ak = (tid & 1) * 8;          // 0 or 8
    const int bk = tid >> 5;               // 0..7 (and +8)
    const int bn = (lane) * 4;             // 0..124

    float c[4][4][4] = {};                 // [mi][ni][frag]
    float4 ar0, ar1, br0, br1;

    // load tile 0 into smem
    {
        ar0 = *(const float4*)(Ab + (size_t)am * K + ak);
        ar1 = *(const float4*)(Ab + (size_t)am * K + ak + 4);
        br0 = *(const float4*)(Bb + (size_t)bk * N + bn);
        br1 = *(const float4*)(Bb + (size_t)(bk + 8) * N + bn);
        float* ap = &As[am][ak];
        ap[0]=__uint_as_float(f2tf(ar0.x)); ap[1]=__uint_as_float(f2tf(ar0.y));
        ap[2]=__uint_as_float(f2tf(ar0.z)); ap[3]=__uint_as_float(f2tf(ar0.w));
        ap[4]=__uint_as_float(f2tf(ar1.x)); ap[5]=__uint_as_float(f2tf(ar1.y));
        ap[6]=__uint_as_float(f2tf(ar1.z)); ap[7]=__uint_as_float(f2tf(ar1.w));
        float* bp0 = &Bs[bk][bn];
        bp0[0]=__uint_as_float(f2tf(br0.x)); bp0[1]=__uint_as_float(f2tf(br0.y));
        bp0[2]=__uint_as_float(f2tf(br0.z)); bp0[3]=__uint_as_float(f2tf(br0.w));
        float* bp1 = &Bs[bk + 8][bn];
        bp1[0]=__uint_as_float(f2tf(br1.x)); bp1[1]=__uint_as_float(f2tf(br1.y));
        bp1[2]=__uint_as_float(f2tf(br1.z)); bp1[3]=__uint_as_float(f2tf(br1.w));
    }
    __syncthreads();

    const int T = K / BKT;
    for (int t = 0; t < T; t++) {
        // prefetch next tile to registers
        if (t + 1 < T) {
            int k0 = (t + 1) * BKT;
            ar0 = *(const float4*)(Ab + (size_t)am * K + k0 + ak);
            ar1 = *(const float4*)(Ab + (size_t)am * K + k0 + ak + 4);
            br0 = *(const float4*)(Bb + (size_t)(k0 + bk) * N + bn);
            br1 = *(const float4*)(Bb + (size_t)(k0 + bk + 8) * N + bn);
        }

        // compute 2 k-steps of 8
        #pragma unroll
        for (int ks = 0; ks < 2; ks++) {
            const int kc = ks * 8 + tig;
            uint32_t a[4][4], b[4][2];
            #pragma unroll
            for (int mi = 0; mi < 4; mi++) {
                int m0 = wm * 64 + mi * 16 + grp;
                a[mi][0] = __float_as_uint(As[m0    ][kc    ]);
                a[mi][1] = __float_as_uint(As[m0 + 8][kc    ]);
                a[mi][2] = __float_as_uint(As[m0    ][kc + 4]);
                a[mi][3] = __float_as_uint(As[m0 + 8][kc + 4]);
            }
            #pragma unroll
            for (int ni = 0; ni < 4; ni++) {
                int n0 = wn * 32 + ni * 8 + grp;
                b[ni][0] = __float_as_uint(Bs[ks * 8 + tig    ][n0]);
                b[ni][1] = __float_as_uint(Bs[ks * 8 + tig + 4][n0]);
            }
            #pragma unroll
            for (int mi = 0; mi < 4; mi++)
                #pragma unroll
                for (int ni = 0; ni < 4; ni++)
                    mma_tf32(c[mi][ni], a[mi][0], a[mi][1], a[mi][2], a[mi][3],
                             b[ni][0], b[ni][1]);
        }
        __syncthreads();

        if (t + 1 < T) {
            float* ap = &As[am][ak];
            ap[0]=__uint_as_float(f2tf(ar0.x)); ap[1]=__uint_as_float(f2tf(ar0.y));
            ap[2]=__uint_as_float(f2tf(ar0.z)); ap[3]=__uint_as_float(f2tf(ar0.w));
            ap[4]=__uint_as_float(f2tf(ar1.x)); ap[5]=__uint_as_float(f2tf(ar1.y));
            ap[6]=__uint_as_float(f2tf(ar1.z)); ap[7]=__uint_as_float(f2tf(ar1.w));
            float* bp0 = &Bs[bk][bn];
            bp0[0]=__uint_as_float(f2tf(br0.x)); bp0[1]=__uint_as_float(f2tf(br0.y));
            bp0[2]=__uint_as_float(f2tf(br0.z)); bp0[3]=__uint_as_float(f2tf(br0.w));
            float* bp1 = &Bs[bk + 8][bn];
            bp1[0]=__uint_as_float(f2tf(br1.x)); bp1[1]=__uint_as_float(f2tf(br1.y));
            bp1[2]=__uint_as_float(f2tf(br1.z)); bp1[3]=__uint_as_float(f2tf(br1.w));
            __syncthreads();
        }
    }

    // epilogue
    #pragma unroll
    for (int mi = 0; mi < 4; mi++) {
        #pragma unroll
        for (int rr = 0; rr < 2; rr++) {
            int m = cRow * BM + wm * 64 + mi * 16 + grp + rr * 8;
            int outm = (mode == 3) ? map_row(m) : m;
            #pragma unroll
            for (int ni = 0; ni < 4; ni++) {
                int n = cCol * BN + wn * 32 + ni * 8 + tig * 2;
                float v0 = c[mi][ni][rr * 2 + 0] + bias[n];
                float v1 = c[mi][ni][rr * 2 + 1] + bias[n + 1];
                if (mode == 1) {
                    v0 = 0.5f * v0 * (1.0f + erff(v0 * 0.70710678118654752f));
                    v1 = 0.5f * v1 * (1.0f + erff(v1 * 0.70710678118654752f));
                } else if (mode == 2) {
                    v0 += res[(size_t)m * N + n];
                    v1 += res[(size_t)m * N + n + 1];
                } else if (mode == 3) {
                    v0 += res[(size_t)outm * N + n];
                    v1 += res[(size_t)outm * N + n + 1];
                }
                C[(size_t)outm * N + n]     = v0;
                C[(size_t)outm * N + n + 1] = v1;
            }
        }
    }
}

// Windowed attention: one block per (window, head).
__global__ __launch_bounds__(128) void attn_kernel(
    const float* __restrict__ q, const float* __restrict__ k,
    const float* __restrict__ v, const float* __restrict__ rel_table,
    const int* __restrict__ rel_index, float* __restrict__ ctx)
{
    __shared__ float qs[W2_][HD_];
    __shared__ float ks[W2_][HD_];
    __shared__ float vs[W2_][HD_];
    __shared__ float sc[W2_][W2_ + 1];
    __shared__ int   grp[W2_];

    int blk  = blockIdx.x;
    int head = blk & (HEADS_ - 1);
    int win  = blk >> 4;
    int w    = win & (NW_ - 1);
    int tid  = threadIdx.x;

    const size_t base = (size_t)win * W2_ * C_ + head * HD_;
    for (int idx = tid; idx < W2_ * HD_; idx += 128) {
        int t = idx >> 5, d = idx & 31;
        size_t off = base + (size_t)t * C_ + d;
        qs[t][d] = q[off];
        ks[t][d] = k[off];
        vs[t][d] = v[off];
    }
    if (tid < W2_) {
        int wh = w >> 2, ww = w & 3;
        int r = wh * WS_ + tid / WS_;
        int c = ww * WS_ + tid % WS_;
        int br = (r < HDIM - WS_) ? 0 : ((r < HDIM - SHIFT_) ? 1 : 2);
        int bc = (c < WDIM - WS_) ? 0 : ((c < WDIM - SHIFT_) ? 1 : 2);
        grp[tid] = br * 3 + bc;
    }
    __syncthreads();

    const float scale = 0.17677669529663687f; // 1/sqrt(32)
    for (int idx = tid; idx < W2_ * W2_; idx += 128) {
        int i = idx / W2_, j = idx - i * W2_;
        float acc = 0.0f;
        #pragma unroll
        for (int d = 0; d < HD_; d++) acc = fmaf(qs[i][d], ks[j][d], acc);
        float bias = rel_table[rel_index[idx] * HEADS_ + head];
        float mask = (grp[i] != grp[j]) ? -100.0f : 0.0f;
        sc[i][j] = acc * scale + bias + mask;
    }
    __syncthreads();

    if (tid < W2_) {
        float mx = -1e30f;
        #pragma unroll 7
        for (int j = 0; j < W2_; j++) mx = fmaxf(mx, sc[tid][j]);
        float sum = 0.0f;
        #pragma unroll 7
        for (int j = 0; j < W2_; j++) {
            float e = __expf(sc[tid][j] - mx);
            sc[tid][j] = e;
            sum += e;
        }
        float inv = 1.0f / sum;
        #pragma unroll 7
        for (int j = 0; j < W2_; j++) sc[tid][j] *= inv;
    }
    __syncthreads();

    for (int idx = tid; idx < W2_ * HD_; idx += 128) {
        int i = idx >> 5, d = idx & 31;
        float acc = 0.0f;
        #pragma unroll 7
        for (int j = 0; j < W2_; j++) acc = fmaf(sc[i][j], vs[j][d], acc);
        ctx[base + (size_t)i * C_ + d] = acc;
    }
}

extern "C" void kernel_launch(void* const* d_in, const int* in_sizes, int n_in,
                              void* d_out, int out_size)
{
    const float* x         = (const float*)d_in[0];
    const float* g1        = (const float*)d_in[1];
    const float* b1        = (const float*)d_in[2];
    const float* wq        = (const float*)d_in[3];
    const float* bq        = (const float*)d_in[4];
    const float* wk        = (const float*)d_in[5];
    const float* bk        = (const float*)d_in[6];
    const float* wv        = (const float*)d_in[7];
    const float* bv        = (const float*)d_in[8];
    const float* rel_table = (const float*)d_in[9];
    const float* wo        = (const float*)d_in[10];
    const float* bo        = (const float*)d_in[11];
    const float* g2        = (const float*)d_in[12];
    const float* b2        = (const float*)d_in[13];
    const float* wi        = (const float*)d_in[14];
    const float* bi        = (const float*)d_in[15];
    const float* w_out     = (const float*)d_in[16];
    const float* b_out     = (const float*)d_in[17];
    const int*   rel_index = (const int*)d_in[18];
    float* out = (float*)d_out;

    float *p_win, *p_q, *p_k, *p_v, *p_ctx, *p_x1, *p_h2, *p_mid;
    cudaGetSymbolAddress((void**)&p_win, g_win);
    cudaGetSymbolAddress((void**)&p_q,   g_q);
    cudaGetSymbolAddress((void**)&p_k,   g_k);
    cudaGetSymbolAddress((void**)&p_v,   g_v);
    cudaGetSymbolAddress((void**)&p_ctx, g_ctx);
    cudaGetSymbolAddress((void**)&p_x1,  g_x1);
    cudaGetSymbolAddress((void**)&p_h2,  g_h2);
    cudaGetSymbolAddress((void**)&p_mid, g_mid);

    // 1. LN1 + cyclic shift + window partition (gather)
    ln_kernel<<<MTOK, 128>>>(x, g1, b1, p_win, 1);

    // 2-4. QKV projections
    dim3 gC(C_ / BN, MTOK / BM);
    tgemm_kernel<<<gC, 256>>>(p_win, wq, bq, p_q, MTOK, C_, C_, 0, nullptr);
    tgemm_kernel<<<gC, 256>>>(p_win, wk, bk, p_k, MTOK, C_, C_, 0, nullptr);
    tgemm_kernel<<<gC, 256>>>(p_win, wv, bv, p_v, MTOK, C_, C_, 0, nullptr);

    // 5. windowed attention (scores + bias + mask + softmax + PV)
    attn_kernel<<<NWIN * HEADS_, 128>>>(p_q, p_k, p_v, rel_table, rel_index, p_ctx);

    // 6. output projection + window reverse + un-shift scatter + residual(x)
    tgemm_kernel<<<gC, 256>>>(p_ctx, wo, bo, p_x1, MTOK, C_, C_, 3, x);

    // 7. LN2
    ln_kernel<<<MTOK, 128>>>(p_x1, g2, b2, p_h2, 0);

    // 8. MLP up-projection + exact GELU
    dim3 gM(MLPD / BN, MTOK / BM);
    tgemm_kernel<<<gM, 256>>>(p_h2, wi, bi, p_mid, MTOK, MLPD, C_, 1, nullptr);

    // 9. MLP down-projection + residual(x1) -> final output
    tgemm_kernel<<<gC, 256>>>(p_mid, w_out, b_out, out, MTOK, C_, MLPD, 2, p_x1);
}

// round 3
// speedup vs baseline: 2.6797x; 1.2834x over previous
#include <cuda_runtime.h>
#include <math.h>
#include <stdint.h>

// Problem constants
#define BATCH   64
#define HDIM    28
#define WDIM    28
#define C_      512
#define HEADS_  16
#define WS_     7
#define SHIFT_  3
#define MLPD    2048
#define HD_     32
#define W2_     49
#define NW_     16
#define HW_     784
#define MTOK    50176   // BATCH*HW
#define NWIN    1024    // BATCH*NW

// Scratch (device globals: no allocation allowed in kernel_launch)
__device__ float g_win[MTOK * C_];
__device__ float g_q[MTOK * C_];
__device__ float g_k[MTOK * C_];
__device__ float g_v[MTOK * C_];
__device__ float g_ctx[MTOK * C_];
__device__ float g_x1[MTOK * C_];
__device__ float g_h2[MTOK * C_];
__device__ float g_mid[(size_t)MTOK * MLPD];

// Map window-partition row m -> token row in the unshifted [B,H*W] layout.
__device__ __forceinline__ int map_row(int m) {
    int bb  = m / HW_;
    int rem = m - bb * HW_;
    int w   = rem / W2_;
    int t   = rem - w * W2_;
    int wh = w >> 2, ww = w & 3;
    int th = t / WS_, tw = t - th * WS_;
    int r = wh * WS_ + th + SHIFT_; if (r >= HDIM) r -= HDIM;
    int c = ww * WS_ + tw + SHIFT_; if (c >= WDIM) c -= WDIM;
    return bb * HW_ + r * WDIM + c;
}

// LayerNorm over C=512, one block per token row.
__global__ __launch_bounds__(128) void ln_kernel(
    const float* __restrict__ in, const float* __restrict__ g,
    const float* __restrict__ b, float* __restrict__ out, int gather)
{
    int m = blockIdx.x;
    int src = gather ? map_row(m) : m;
    int tid = threadIdx.x;

    float4 xv = ((const float4*)(in + (size_t)src * C_))[tid];
    float s  = xv.x + xv.y + xv.z + xv.w;
    float s2 = xv.x*xv.x + xv.y*xv.y + xv.z*xv.z + xv.w*xv.w;
    #pragma unroll
    for (int off = 16; off; off >>= 1) {
        s  += __shfl_xor_sync(0xffffffffu, s,  off);
        s2 += __shfl_xor_sync(0xffffffffu, s2, off);
    }
    __shared__ float red[8];
    int wid = tid >> 5;
    if ((tid & 31) == 0) { red[wid] = s; red[4 + wid] = s2; }
    __syncthreads();
    s  = red[0] + red[1] + red[2] + red[3];
    s2 = red[4] + red[5] + red[6] + red[7];
    float mu   = s * (1.0f / C_);
    float var  = fmaf(-mu, mu, s2 * (1.0f / C_));
    float rstd = rsqrtf(var + 1e-5f);

    float4 gv = ((const float4*)g)[tid];
    float4 bv = ((const float4*)b)[tid];
    float4 o;
    o.x = (xv.x - mu) * rstd * gv.x + bv.x;
    o.y = (xv.y - mu) * rstd * gv.y + bv.y;
    o.z = (xv.z - mu) * rstd * gv.z + bv.z;
    o.w = (xv.w - mu) * rstd * gv.w + bv.w;
    ((float4*)(out + (size_t)m * C_))[tid] = o;
}

// ---------------------------------------------------------------------------
// TF32 tensor-core GEMM with cp.async double buffering.
// C[M,N] = A[M,K] @ B[K,N] + bias, epilogue modes.
// 256 threads = 8 warps (2 x 4), block tile 128x128, BK=16, warp tile 64x32.
// fp32 operands fed to mma.tf32 directly (HW truncation).
// mode 0: plain   mode 1: exact GELU   mode 2: += res[m]
// mode 3: scatter row via map_row(m), += res[out_row]
// ---------------------------------------------------------------------------
#define BM 128
#define BN 128
#define BKT 16
#define ASTR 20   // As row stride (floats): conflict-free (20g+t covers banks)
#define BSTR 136  // Bs row stride (floats): 136 mod 32 = 8 -> 8t+g covers banks

__device__ __forceinline__ void cpa16(void* smem_dst, const void* gsrc) {
    uint32_t s = (uint32_t)__cvta_generic_to_shared(smem_dst);
    asm volatile("cp.async.cg.shared.global [%0], [%1], 16;\n" :: "r"(s), "l"(gsrc));
}

__device__ __forceinline__ void mma_tf32(float c[4], uint32_t a0, uint32_t a1,
                                         uint32_t a2, uint32_t a3,
                                         uint32_t b0, uint32_t b1) {
    asm volatile(
        "mma.sync.aligned.m16n8k8.row.col.f32.tf32.tf32.f32 "
        "{%0,%1,%2,%3}, {%4,%5,%6,%7}, {%8,%9}, {%0,%1,%2,%3};"
        : "+f"(c[0]), "+f"(c[1]), "+f"(c[2]), "+f"(c[3])
        : "r"(a0), "r"(a1), "r"(a2), "r"(a3), "r"(b0), "r"(b1));
}

__global__ __launch_bounds__(256) void tgemm_kernel(
    const float* __restrict__ A, const float* __restrict__ Bm,
    const float* __restrict__ bias, float* __restrict__ C,
    int M, int N, int K, int mode, const float* __restrict__ res)
{
    __shared__ float As[2][BM * ASTR];
    __shared__ float Bs[2][BKT * BSTR];

    const int cRow = blockIdx.y, cCol = blockIdx.x;
    const int tid  = threadIdx.x;
    const int wid  = tid >> 5;
    const int lane = tid & 31;
    const int wm   = wid >> 2;       // 0..1
    const int wn   = wid & 3;        // 0..3
    const int grp  = lane >> 2;      // 0..7
    const int tig  = lane & 3;       // 0..3

    const float* Ab = A  + (size_t)cRow * BM * K;
    const float* Bb = Bm + (size_t)cCol * BN;

    // cp.async mapping: 2 A chunks + 2 B chunks per thread per tile
    const int aRow0 = tid >> 1;              // chunk0: row = tid*2 >> 2
    // chunks c = tid*2, tid*2+1: row = c>>2, k4 = (c&3)*4
    const int bRowBase = tid >> 4;           // c>>5 for c = tid*2 -> tid>>4... compute inline

    float c[4][4][4] = {};

    auto load_tile = [&](int t, int s) {
        int k0 = t * BKT;
        #pragma unroll
        for (int cc = 0; cc < 2; cc++) {
            int id = tid * 2 + cc;
            int ar = id >> 2, ak = (id & 3) * 4;
            cpa16(&As[s][ar * ASTR + ak], Ab + (size_t)ar * K + k0 + ak);
            int br = id >> 5, bn = (id & 31) * 4;
            cpa16(&Bs[s][br * BSTR + bn], Bb + (size_t)(k0 + br) * N + bn);
        }
        asm volatile("cp.async.commit_group;\n");
    };
    (void)aRow0; (void)bRowBase;

    const int T = K / BKT;
    load_tile(0, 0);

    for (int t = 0; t < T; t++) {
        if (t + 1 < T) {
            load_tile(t + 1, (t + 1) & 1);
            asm volatile("cp.async.wait_group 1;\n");
        } else {
            asm volatile("cp.async.wait_group 0;\n");
        }
        __syncthreads();

        const float* Asb = As[t & 1];
        const float* Bsb = Bs[t & 1];

        #pragma unroll
        for (int ks = 0; ks < 2; ks++) {
            const int kc = ks * 8 + tig;
            uint32_t a[4][4], b[4][2];
            #pragma unroll
            for (int mi = 0; mi < 4; mi++) {
                int m0 = wm * 64 + mi * 16 + grp;
                a[mi][0] = __float_as_uint(Asb[(m0    ) * ASTR + kc    ]);
                a[mi][1] = __float_as_uint(Asb[(m0 + 8) * ASTR + kc    ]);
                a[mi][2] = __float_as_uint(Asb[(m0    ) * ASTR + kc + 4]);
                a[mi][3] = __float_as_uint(Asb[(m0 + 8) * ASTR + kc + 4]);
            }
            #pragma unroll
            for (int ni = 0; ni < 4; ni++) {
                int n0 = wn * 32 + ni * 8 + grp;
                b[ni][0] = __float_as_uint(Bsb[(ks * 8 + tig    ) * BSTR + n0]);
                b[ni][1] = __float_as_uint(Bsb[(ks * 8 + tig + 4) * BSTR + n0]);
            }
            #pragma unroll
            for (int mi = 0; mi < 4; mi++)
                #pragma unroll
                for (int ni = 0; ni < 4; ni++)
                    mma_tf32(c[mi][ni], a[mi][0], a[mi][1], a[mi][2], a[mi][3],
                             b[ni][0], b[ni][1]);
        }
        __syncthreads();
    }

    // epilogue
    #pragma unroll
    for (int mi = 0; mi < 4; mi++) {
        #pragma unroll
        for (int rr = 0; rr < 2; rr++) {
            int m = cRow * BM + wm * 64 + mi * 16 + grp + rr * 8;
            int outm = (mode == 3) ? map_row(m) : m;
            #pragma unroll
            for (int ni = 0; ni < 4; ni++) {
                int n = cCol * BN + wn * 32 + ni * 8 + tig * 2;
                float v0 = c[mi][ni][rr * 2 + 0] + bias[n];
                float v1 = c[mi][ni][rr * 2 + 1] + bias[n + 1];
                if (mode == 1) {
                    v0 = 0.5f * v0 * (1.0f + erff(v0 * 0.70710678118654752f));
                    v1 = 0.5f * v1 * (1.0f + erff(v1 * 0.70710678118654752f));
                } else if (mode == 2) {
                    v0 += res[(size_t)m * N + n];
                    v1 += res[(size_t)m * N + n + 1];
                } else if (mode == 3) {
                    v0 += res[(size_t)outm * N + n];
                    v1 += res[(size_t)outm * N + n + 1];
                }
                C[(size_t)outm * N + n]     = v0;
                C[(size_t)outm * N + n + 1] = v1;
            }
        }
    }
}

// Windowed attention: one block per (window, head).
// smem tiles padded to stride 33 -> conflict-free ks[j][d] access in scores.
#define HDP 33
__global__ __launch_bounds__(128) void attn_kernel(
    const float* __restrict__ q, const float* __restrict__ k,
    const float* __restrict__ v, const float* __restrict__ rel_table,
    const int* __restrict__ rel_index, float* __restrict__ ctx)
{
    __shared__ float qs[W2_][HDP];
    __shared__ float ks[W2_][HDP];
    __shared__ float vs[W2_][HDP];
    __shared__ float sc[W2_][W2_ + 1];
    __shared__ int   grp[W2_];

    int blk  = blockIdx.x;
    int head = blk & (HEADS_ - 1);
    int win  = blk >> 4;
    int w    = win & (NW_ - 1);
    int tid  = threadIdx.x;

    const size_t base = (size_t)win * W2_ * C_ + head * HD_;
    for (int idx = tid; idx < W2_ * HD_; idx += 128) {
        int t = idx >> 5, d = idx & 31;
        size_t off = base + (size_t)t * C_ + d;
        qs[t][d] = q[off];
        ks[t][d] = k[off];
        vs[t][d] = v[off];
    }
    if (tid < W2_) {
        int wh = w >> 2, ww = w & 3;
        int r = wh * WS_ + tid / WS_;
        int c = ww * WS_ + tid % WS_;
        int br = (r < HDIM - WS_) ? 0 : ((r < HDIM - SHIFT_) ? 1 : 2);
        int bc = (c < WDIM - WS_) ? 0 : ((c < WDIM - SHIFT_) ? 1 : 2);
        grp[tid] = br * 3 + bc;
    }
    __syncthreads();

    const float scale = 0.17677669529663687f; // 1/sqrt(32)
    for (int idx = tid; idx < W2_ * W2_; idx += 128) {
        int i = idx / W2_, j = idx - i * W2_;
        float acc = 0.0f;
        #pragma unroll
        for (int d = 0; d < HD_; d++) acc = fmaf(qs[i][d], ks[j][d], acc);
        float bias = rel_table[rel_index[idx] * HEADS_ + head];
        float mask = (grp[i] != grp[j]) ? -100.0f : 0.0f;
        sc[i][j] = acc * scale + bias + mask;
    }
    __syncthreads();

    if (tid < W2_) {
        float mx = -1e30f;
        #pragma unroll 7
        for (int j = 0; j < W2_; j++) mx = fmaxf(mx, sc[tid][j]);
        float sum = 0.0f;
        #pragma unroll 7
        for (int j = 0; j < W2_; j++) {
            float e = __expf(sc[tid][j] - mx);
            sc[tid][j] = e;
            sum += e;
        }
        float inv = 1.0f / sum;
        #pragma unroll 7
        for (int j = 0; j < W2_; j++) sc[tid][j] *= inv;
    }
    __syncthreads();

    for (int idx = tid; idx < W2_ * HD_; idx += 128) {
        int i = idx >> 5, d = idx & 31;
        float acc = 0.0f;
        #pragma unroll 7
        for (int j = 0; j < W2_; j++) acc = fmaf(sc[i][j], vs[j][d], acc);
        ctx[base + (size_t)i * C_ + d] = acc;
    }
}

extern "C" void kernel_launch(void* const* d_in, const int* in_sizes, int n_in,
                              void* d_out, int out_size)
{
    const float* x         = (const float*)d_in[0];
    const float* g1        = (const float*)d_in[1];
    const float* b1        = (const float*)d_in[2];
    const float* wq        = (const float*)d_in[3];
    const float* bq        = (const float*)d_in[4];
    const float* wk        = (const float*)d_in[5];
    const float* bk        = (const float*)d_in[6];
    const float* wv        = (const float*)d_in[7];
    const float* bv        = (const float*)d_in[8];
    const float* rel_table = (const float*)d_in[9];
    const float* wo        = (const float*)d_in[10];
    const float* bo        = (const float*)d_in[11];
    const float* g2        = (const float*)d_in[12];
    const float* b2        = (const float*)d_in[13];
    const float* wi        = (const float*)d_in[14];
    const float* bi        = (const float*)d_in[15];
    const float* w_out     = (const float*)d_in[16];
    const float* b_out     = (const float*)d_in[17];
    const int*   rel_index = (const int*)d_in[18];
    float* out = (float*)d_out;

    float *p_win, *p_q, *p_k, *p_v, *p_ctx, *p_x1, *p_h2, *p_mid;
    cudaGetSymbolAddress((void**)&p_win, g_win);
    cudaGetSymbolAddress((void**)&p_q,   g_q);
    cudaGetSymbolAddress((void**)&p_k,   g_k);
    cudaGetSymbolAddress((void**)&p_v,   g_v);
    cudaGetSymbolAddress((void**)&p_ctx, g_ctx);
    cudaGetSymbolAddress((void**)&p_x1,  g_x1);
    cudaGetSymbolAddress((void**)&p_h2,  g_h2);
    cudaGetSymbolAddress((void**)&p_mid, g_mid);

    // 1. LN1 + cyclic shift + window partition (gather)
    ln_kernel<<<MTOK, 128>>>(x, g1, b1, p_win, 1);

    // 2-4. QKV projections
    dim3 gC(C_ / BN, MTOK / BM);
    tgemm_kernel<<<gC, 256>>>(p_win, wq, bq, p_q, MTOK, C_, C_, 0, nullptr);
    tgemm_kernel<<<gC, 256>>>(p_win, wk, bk, p_k, MTOK, C_, C_, 0, nullptr);
    tgemm_kernel<<<gC, 256>>>(p_win, wv, bv, p_v, MTOK, C_, C_, 0, nullptr);

    // 5. windowed attention (scores + bias + mask + softmax + PV)
    attn_kernel<<<NWIN * HEADS_, 128>>>(p_q, p_k, p_v, rel_table, rel_index, p_ctx);

    // 6. output projection + window reverse + un-shift scatter + residual(x)
    tgemm_kernel<<<gC, 256>>>(p_ctx, wo, bo, p_x1, MTOK, C_, C_, 3, x);

    // 7. LN2
    ln_kernel<<<MTOK, 128>>>(p_x1, g2, b2, p_h2, 0);

    // 8. MLP up-projection + exact GELU
    dim3 gM(MLPD / BN, MTOK / BM);
    tgemm_kernel<<<gM, 256>>>(p_h2, wi, bi, p_mid, MTOK, MLPD, C_, 1, nullptr);

    // 9. MLP down-projection + residual(x1) -> final output
    tgemm_kernel<<<gC, 256>>>(p_mid, w_out, b_out, out, MTOK, C_, MLPD, 2, p_x1);
}